// round 5
// baseline (speedup 1.0000x reference)
#include <cuda_runtime.h>
#include <cstdint>
#include <cstddef>

// ============================================================================
// StackedLoRALinear on GB300 — generic-target build (PTX .target sm_103, no
// 'a' suffix), so tcgen05/TMEM are unavailable. Use stable-PTX tf32
// mma.sync.m16n8k8 (fallback HMMA pipe) with a cp.async multistage pipeline.
//
//   out[m][n] = b[n] + sum_{k<3072} x[m,k]*W[n,k] + sum_{j<128} z[m,j]*Bp[n,j]
//   z[m][j]   = sum_k x[m,k]*Aflat[j,k]   (Aflat = lora_A as 128x3072)
//   Bp[n][j]  = lora_B[d][n][r],  j = d*32+r
// All GEMM operands pre-rounded to tf32 with cvt.rna (incl. x) so the mma's
// implicit truncation is exact round-to-nearest.
// ============================================================================

#define DEV __device__ __forceinline__

static constexpr int D_DIM  = 3072;
static constexpr int M_ROWS = 16384;     // 4 * 4096
static constexpr int R_DIM  = 128;       // depth * rank

static constexpr int BM = 128, BN = 128, BK = 32;
static constexpr int STAGES = 4;
static constexpr int LDSS = 36;                       // smem row stride (floats)
static constexpr int STAGE_FLOATS = (BM + BN) * LDSS; // 9216
static constexpr int SMEM_BYTES = STAGES * STAGE_FLOATS * 4;  // 147456

// ---------------- scratch (static device globals; no allocation) ------------
__device__ float g_xr[(size_t)M_ROWS * D_DIM];  // rounded x        (201 MB)
__device__ float g_Wr[D_DIM * D_DIM];           // rounded W        (37.75 MB)
__device__ float g_Ar[R_DIM * D_DIM];           // rounded lora_A   (1.5 MB)
__device__ float g_Bp[D_DIM * R_DIM];           // packed lora_B    (1.5 MB)
__device__ float g_z [(size_t)M_ROWS * R_DIM];  // z = x @ Aflat^T  (8 MB)

// ---------------- helpers ----------------------------------------------------
DEV uint32_t smem_u32(const void* p) {
    uint32_t a;
    asm("{ .reg .u64 t; cvta.to.shared.u64 t, %1; cvt.u32.u64 %0, t; }"
        : "=r"(a) : "l"(p));
    return a;
}

DEV void cp16(uint32_t s, const void* g) {
    asm volatile("cp.async.cg.shared.global [%0], [%1], 16;\n"
                 :: "r"(s), "l"(g));
}

DEV float rna_tf32(float x) {
    uint32_t o;
    asm("cvt.rna.tf32.f32 %0, %1;" : "=r"(o) : "f"(x));
    return __uint_as_float(o);
}

DEV void mma16n8k8(float c[4],
                   uint32_t a0, uint32_t a1, uint32_t a2, uint32_t a3,
                   uint32_t b0, uint32_t b1) {
    asm volatile(
        "mma.sync.aligned.m16n8k8.row.col.f32.tf32.tf32.f32 "
        "{%0,%1,%2,%3}, {%4,%5,%6,%7}, {%8,%9}, {%0,%1,%2,%3};"
        : "+f"(c[0]), "+f"(c[1]), "+f"(c[2]), "+f"(c[3])
        : "r"(a0), "r"(a1), "r"(a2), "r"(a3), "r"(b0), "r"(b1));
}

// ---------------- prep: tf32-round everything + pack lora_B -----------------
__global__ void prep_kernel(const float* __restrict__ x,
                            const float* __restrict__ W,
                            const float* __restrict__ lA,
                            const float* __restrict__ lB) {
    const size_t stride = (size_t)gridDim.x * blockDim.x;
    const size_t g0 = (size_t)blockIdx.x * blockDim.x + threadIdx.x;
    for (size_t i = g0; i < (size_t)M_ROWS * D_DIM; i += stride)
        g_xr[i] = rna_tf32(x[i]);
    for (size_t i = g0; i < (size_t)D_DIM * D_DIM; i += stride)
        g_Wr[i] = rna_tf32(W[i]);
    for (size_t i = g0; i < (size_t)R_DIM * D_DIM; i += stride)
        g_Ar[i] = rna_tf32(lA[i]);
    for (size_t i = g0; i < (size_t)D_DIM * R_DIM; i += stride) {
        int n = (int)(i >> 7), j = (int)(i & 127);
        int d = j >> 5, r = j & 31;
        g_Bp[i] = rna_tf32(lB[(size_t)(d * D_DIM + n) * 32 + r]);
    }
}

// ---------------- tf32 mma.sync GEMM, dual K-source, bias epilogue ----------
// C[m][n] = bias[n] + sum_{K1} A1[m,k]*B1[n,k] + sum_{K2} A2[m,k]*B2[n,k]
// CTA 128x128, 8 warps in 2(M) x 4(N), warp tile 64x32, BK=32, 4-stage pipe.
__global__ void __launch_bounds__(256, 1)
gemm_tf32_mma(const float* __restrict__ A1, int lda1,
              const float* __restrict__ B1, int ldb1, int K1,
              const float* __restrict__ A2, int lda2,
              const float* __restrict__ B2, int ldb2, int K2,
              const float* __restrict__ bias,
              float* __restrict__ C, int ldc)
{
    extern __shared__ __align__(16) float smem[];
    const uint32_t sbase = smem_u32(smem);

    const int tid  = threadIdx.x;
    const int wid  = tid >> 5;
    const int lane = tid & 31;
    const int g    = lane >> 2;       // 0..7
    const int tig  = lane & 3;        // 0..3
    const int wm   = (wid & 1) * 64;  // warp M offset in CTA tile
    const int wn   = (wid >> 1) * 32; // warp N offset in CTA tile

    const int mBase = blockIdx.y * BM;
    const int nBase = blockIdx.x * BN;
    const int NT = (K1 + K2) / BK;

    float acc[4][4][4];
    #pragma unroll
    for (int mi = 0; mi < 4; ++mi)
        #pragma unroll
        for (int ni = 0; ni < 4; ++ni)
            #pragma unroll
            for (int c = 0; c < 4; ++c) acc[mi][ni][c] = 0.f;

    auto load_tile = [&](int kt) {
        if (kt < NT) {
            const float* Ap; const float* Bq; int lda, ldb, kOff;
            if (kt * BK < K1) { Ap = A1; Bq = B1; lda = lda1; ldb = ldb1; kOff = kt * BK; }
            else              { Ap = A2; Bq = B2; lda = lda2; ldb = ldb2; kOff = kt * BK - K1; }
            const uint32_t st = sbase + (uint32_t)((kt % STAGES) * STAGE_FLOATS * 4);
            #pragma unroll
            for (int i = 0; i < 4; ++i) {             // A: 1024 chunks / 256 thr
                int chunk = tid + i * 256;
                int row = chunk >> 3, c = chunk & 7;  // 8 x 16B per row (BK=32 f32)
                cp16(st + (uint32_t)(row * LDSS + c * 4) * 4,
                     Ap + (size_t)(mBase + row) * lda + kOff + c * 4);
            }
            const uint32_t stB = st + (uint32_t)(BM * LDSS * 4);
            #pragma unroll
            for (int i = 0; i < 4; ++i) {             // B: 1024 chunks / 256 thr
                int chunk = tid + i * 256;
                int row = chunk >> 3, c = chunk & 7;
                cp16(stB + (uint32_t)(row * LDSS + c * 4) * 4,
                     Bq + (size_t)(nBase + row) * ldb + kOff + c * 4);
            }
        }
        asm volatile("cp.async.commit_group;\n" ::: "memory"); // commit even if empty
    };

    // prologue: STAGES-1 tiles in flight
    for (int s = 0; s < STAGES - 1; ++s) load_tile(s);

    for (int kt = 0; kt < NT; ++kt) {
        asm volatile("cp.async.wait_group %0;\n" :: "n"(STAGES - 2) : "memory");
        __syncthreads();               // tile kt visible; slot (kt-1)%S reusable

        load_tile(kt + STAGES - 1);    // overlap next loads with compute

        const float* As = smem + (kt % STAGES) * STAGE_FLOATS;
        const float* Bs = As + BM * LDSS;

        #pragma unroll
        for (int k8 = 0; k8 < BK; k8 += 8) {
            uint32_t a[4][4];
            #pragma unroll
            for (int mi = 0; mi < 4; ++mi) {
                const float* ap = As + (wm + mi * 16 + g) * LDSS + k8 + tig;
                a[mi][0] = __float_as_uint(ap[0]);
                a[mi][1] = __float_as_uint(ap[8 * LDSS]);
                a[mi][2] = __float_as_uint(ap[4]);
                a[mi][3] = __float_as_uint(ap[8 * LDSS + 4]);
            }
            uint32_t b[4][2];
            #pragma unroll
            for (int ni = 0; ni < 4; ++ni) {
                const float* bp = Bs + (wn + ni * 8 + g) * LDSS + k8 + tig;
                b[ni][0] = __float_as_uint(bp[0]);
                b[ni][1] = __float_as_uint(bp[4]);
            }
            #pragma unroll
            for (int mi = 0; mi < 4; ++mi)
                #pragma unroll
                for (int ni = 0; ni < 4; ++ni)
                    mma16n8k8(acc[mi][ni],
                              a[mi][0], a[mi][1], a[mi][2], a[mi][3],
                              b[ni][0], b[ni][1]);
        }
    }

    // -------- epilogue: +bias, float2 stores -------------------------------
    #pragma unroll
    for (int mi = 0; mi < 4; ++mi) {
        const int m0 = mBase + wm + mi * 16 + g;
        #pragma unroll
        for (int ni = 0; ni < 4; ++ni) {
            const int n0 = nBase + wn + ni * 8 + 2 * tig;
            float bx = 0.f, by = 0.f;
            if (bias) {
                const float2 bv = *reinterpret_cast<const float2*>(bias + n0);
                bx = bv.x; by = bv.y;
            }
            float2 v0 = { acc[mi][ni][0] + bx, acc[mi][ni][1] + by };
            float2 v1 = { acc[mi][ni][2] + bx, acc[mi][ni][3] + by };
            *reinterpret_cast<float2*>(C + (size_t)m0 * ldc + n0)       = v0;
            *reinterpret_cast<float2*>(C + (size_t)(m0 + 8) * ldc + n0) = v1;
        }
    }
}

// ---------------- launch -----------------------------------------------------
extern "C" void kernel_launch(void* const* d_in, const int* in_sizes, int n_in,
                              void* d_out, int out_size) {
    const float* x  = (const float*)d_in[0];   // [4,4096,3072]
    const float* W  = (const float*)d_in[1];   // [3072,3072]
    const float* b  = (const float*)d_in[2];   // [3072]
    const float* lA = (const float*)d_in[3];   // [4,32,3072]
    const float* lB = (const float*)d_in[4];   // [4,3072,32]
    float* out = (float*)d_out;                // [4,4096,3072]

    void *pxr = nullptr, *pWr = nullptr, *pAr = nullptr, *pBp = nullptr, *pz = nullptr;
    cudaGetSymbolAddress(&pxr, g_xr);
    cudaGetSymbolAddress(&pWr, g_Wr);
    cudaGetSymbolAddress(&pAr, g_Ar);
    cudaGetSymbolAddress(&pBp, g_Bp);
    cudaGetSymbolAddress(&pz,  g_z);

    cudaFuncSetAttribute((const void*)gemm_tf32_mma,
                         cudaFuncAttributeMaxDynamicSharedMemorySize, SMEM_BYTES);

    // 1) tf32-round x/W/A, pack+round lora_B
    prep_kernel<<<4096, 256>>>(x, W, lA, lB);

    // 2) z = xr @ Ar^T   (M=16384, N=128, K=3072)
    gemm_tf32_mma<<<dim3(1, M_ROWS / BM), 256, SMEM_BYTES>>>(
        (const float*)pxr, D_DIM, (const float*)pAr, D_DIM, D_DIM,
        nullptr, 0, nullptr, 0, 0,
        nullptr, (float*)pz, R_DIM);

    // 3) out = xr@Wr^T + z@Bp^T + b   (augmented K = 3072 + 128)
    gemm_tf32_mma<<<dim3(D_DIM / BN, M_ROWS / BM), 256, SMEM_BYTES>>>(
        (const float*)pxr, D_DIM, (const float*)pWr, D_DIM, D_DIM,
        (const float*)pz, R_DIM, (const float*)pBp, R_DIM, R_DIM,
        b, out, D_DIM);
}